// round 11
// baseline (speedup 1.0000x reference)
#include <cuda_runtime.h>
#include <cuda_bf16.h>
#include <cfloat>
#include <cstdint>

// Problem constants
#define BB 512
#define LL 128
#define HID 384
#define NLAB 32
#define NSLOT 128
#define NROWS (BB*LL)          // 65536
#define ITERS 3

// ---------------- scratch (static device allocations) ----------------
__device__ float g_T0[NROWS*HID];       // tanh(c) @ W0 (iteration-invariant)
__device__ float g_S [BB*HID];
__device__ float g_y1[BB*HID];
__device__ float g_g [BB*HID];
__device__ float g_rin[BB*HID];
__device__ float g_w3v[HID];
__device__ float g_w4v[HID];
__device__ float g_b4v;
__device__ float g_hdot[NROWS];
// pre-split weights, [N rows][K cols] (K contiguous == col-major B for mma row.col)
__device__ __nv_bfloat16 g_W0h[HID*HID],  g_W0l[HID*HID];
__device__ __nv_bfloat16 g_W2h[HID*HID],  g_W2l[HID*HID];
__device__ __nv_bfloat16 g_Wsh[NSLOT*2*HID], g_Wsl[NSLOT*2*HID];

// ---------------- fast math ----------------
__device__ __forceinline__ float ftanh(float x) {
    float e = __expf(2.0f * x);
    return 1.0f - __fdividef(2.0f, e + 1.0f);
}
__device__ __forceinline__ float fsig(float x) {
    return __fdividef(1.0f, 1.0f + __expf(-x));
}

// ---------------- base-ISA tensor core helpers ----------------
__device__ __forceinline__ uint32_t smem_u32(const void* p) {
    uint32_t a;
    asm("{ .reg .u64 t; cvta.to.shared.u64 t, %1; cvt.u32.u64 %0, t; }" : "=r"(a) : "l"(p));
    return a;
}
__device__ __forceinline__ void ldmx4(uint32_t* r, uint32_t addr) {
    asm volatile("ldmatrix.sync.aligned.m8n8.x4.shared.b16 {%0,%1,%2,%3}, [%4];"
        : "=r"(r[0]), "=r"(r[1]), "=r"(r[2]), "=r"(r[3]) : "r"(addr));
}
__device__ __forceinline__ void mma16816(float* d, const uint32_t* a,
                                         uint32_t b0, uint32_t b1) {
    asm volatile("mma.sync.aligned.m16n8k16.row.col.f32.bf16.bf16.f32 "
        "{%0,%1,%2,%3}, {%4,%5,%6,%7}, {%8,%9}, {%0,%1,%2,%3};"
        : "+f"(d[0]), "+f"(d[1]), "+f"(d[2]), "+f"(d[3])
        : "r"(a[0]), "r"(a[1]), "r"(a[2]), "r"(a[3]), "r"(b0), "r"(b1));
}

// ---------------- big tensor-core GEMM (static smem, BK=32, reg-prefetch pipeline) --
// C[128 rows, 128 cols per CTA] = prologue(A)[128, K] @ B^T, K = KCHN*32.
// grid = (Ntot/128, BB).  8 warps = 4(m) x 2(n); warp tile 32x64.
// AOP: 1=tanh(A)  2=tanh(A + y[b])  3=concat(A=H | A2 * g[b])
// COP: 0=store fp32   1=sigmoid + masked sf-reduction -> C[b, HID] slice
enum { MAOP_TANH = 1, MAOP_T0Y1 = 2, MAOP_CONCAT = 3 };

template <int KCHN, int AOP, int COP>
__global__ void __launch_bounds__(256)
wmma_big(const float* __restrict__ A, const __nv_bfloat16* __restrict__ Bhi,
         const __nv_bfloat16* __restrict__ Blo, float* __restrict__ C, int Ntot,
         const float* __restrict__ xa, const float* __restrict__ xb,
         const float* __restrict__ xc, const int* __restrict__ lens) {
    constexpr int K = KCHN * 32;
    constexpr int LDS = 40;                 // bf16 per smem row (32 + 8 pad -> 80B stride)
    __shared__ __align__(16) __nv_bfloat16 tiles[4][128 * LDS];   // 40960 B
    __shared__ float sy[HID];               // per-b broadcast vector cache
    __nv_bfloat16* sAh = tiles[0];
    __nv_bfloat16* sAl = tiles[1];
    __nv_bfloat16* sBh = tiles[2];
    __nv_bfloat16* sBl = tiles[3];

    int tid = threadIdx.x, lane = tid & 31, wid = tid >> 5;
    int wm = wid & 3, wn = wid >> 2;
    int b = blockIdx.y;
    int bn = blockIdx.x * 128;
    size_t m0 = (size_t)b * 128;

    // cache per-b vector (y1 row for T0Y1, g row for CONCAT)
    if (AOP == MAOP_T0Y1) {
        if (tid < 128) { sy[tid] = xa[(size_t)b * HID + tid];
                         sy[tid + 128] = xa[(size_t)b * HID + tid + 128];
                         sy[tid + 256] = xa[(size_t)b * HID + tid + 256]; }
    } else if (AOP == MAOP_CONCAT) {
        if (tid < 128) { sy[tid] = xb[(size_t)b * HID + tid];
                         sy[tid + 128] = xb[(size_t)b * HID + tid + 128];
                         sy[tid + 256] = xb[(size_t)b * HID + tid + 256]; }
    }

    float acc[2][8][4];
#pragma unroll
    for (int mf = 0; mf < 2; mf++)
#pragma unroll
        for (int nf = 0; nf < 8; nf++)
#pragma unroll
            for (int e = 0; e < 4; e++) acc[mf][nf][e] = 0.f;

    uint32_t aBaseH = smem_u32(sAh), aBaseL = smem_u32(sAl);
    uint32_t bBaseH = smem_u32(sBh), bBaseL = smem_u32(sBl);
    int aRow = wm * 32 + (lane & 15);
    int aK   = (lane & 16) >> 1;                              // 0 / 8
    int bRow = wn * 64 + ((lane & 16) >> 1) + (lane & 7);
    int bK   = lane & 8;

    // per-thread tile coordinates (2 A-iters, 2 B-iters per chunk)
    int arow0 = tid >> 2, ag8_0 = tid & 3;                    // it=0
    int arow1 = (tid + 256) >> 2, ag8_1 = (tid + 256) & 3;    // it=1

    // ---- raw global prefetch (no dependent compute!) ----
    float pA[2][8];
    uint4 pBh[2], pBl[2];
    const uint4* bhp = (const uint4*)Bhi;
    const uint4* blp = (const uint4*)Blo;

    auto loadA = [&](int kc) {
#pragma unroll
        for (int it = 0; it < 2; it++) {
            int row = it ? arow1 : arow0;
            int g8  = it ? ag8_1 : ag8_0;
            int gk  = kc * 32 + g8 * 8;
            const float4* p;
            if (AOP == MAOP_CONCAT && gk >= HID)
                p = (const float4*)(xa + (m0 + row) * HID + (gk - HID));
            else
                p = (const float4*)(A + (m0 + row) * HID + gk);
            float4 a0 = p[0], a1 = p[1];
            pA[it][0]=a0.x; pA[it][1]=a0.y; pA[it][2]=a0.z; pA[it][3]=a0.w;
            pA[it][4]=a1.x; pA[it][5]=a1.y; pA[it][6]=a1.z; pA[it][7]=a1.w;
        }
    };
    auto loadB = [&](int kc) {
#pragma unroll
        for (int it = 0; it < 2; it++) {
            int row = it ? arow1 : arow0;
            int g8  = it ? ag8_1 : ag8_0;
            size_t gi = ((size_t)(bn + row) * K + kc * 32 + g8 * 8) >> 3;
            pBh[it] = bhp[gi];
            pBl[it] = blp[gi];
        }
    };

    loadA(0); loadB(0);
    __syncthreads();          // sy visible before first STS reads it

    for (int kc = 0; kc < KCHN; kc++) {
        if (kc) __syncthreads();          // prior chunk's ldmatrix done before overwrite
        // ---- STS: apply prologue op to prefetched A, split hi/lo; store B ----
#pragma unroll
        for (int it = 0; it < 2; it++) {
            int row = it ? arow1 : arow0;
            int g8  = it ? ag8_1 : ag8_0;
            int gk  = kc * 32 + g8 * 8;
            float v[8];
            if (AOP == MAOP_TANH) {
#pragma unroll
                for (int q = 0; q < 8; q++) v[q] = ftanh(pA[it][q]);
            } else if (AOP == MAOP_T0Y1) {
#pragma unroll
                for (int q = 0; q < 8; q++) v[q] = ftanh(pA[it][q] + sy[gk + q]);
            } else { // MAOP_CONCAT
                if (gk < HID) {
#pragma unroll
                    for (int q = 0; q < 8; q++) v[q] = pA[it][q];
                } else {
                    int k2 = gk - HID;
#pragma unroll
                    for (int q = 0; q < 8; q++) v[q] = pA[it][q] * sy[k2 + q];
                }
            }
            uint4 hu, lu;
            uint32_t* hw = (uint32_t*)&hu;
            uint32_t* lw = (uint32_t*)&lu;
#pragma unroll
            for (int q = 0; q < 4; q++) {
                __nv_bfloat16 h0 = __float2bfloat16(v[2*q]);
                __nv_bfloat16 h1 = __float2bfloat16(v[2*q+1]);
                float l0 = v[2*q]   - __bfloat162float(h0);
                float l1 = v[2*q+1] - __bfloat162float(h1);
                __nv_bfloat16 e0 = __float2bfloat16(l0), e1 = __float2bfloat16(l1);
                hw[q] = (uint32_t)__bfloat16_as_ushort(h0) | ((uint32_t)__bfloat16_as_ushort(h1) << 16);
                lw[q] = (uint32_t)__bfloat16_as_ushort(e0) | ((uint32_t)__bfloat16_as_ushort(e1) << 16);
            }
            *(uint4*)(sAh + row * LDS + g8 * 8) = hu;
            *(uint4*)(sAl + row * LDS + g8 * 8) = lu;
            *(uint4*)(sBh + row * LDS + g8 * 8) = pBh[it];
            *(uint4*)(sBl + row * LDS + g8 * 8) = pBl[it];
        }
        __syncthreads();

        // ---- prefetch next chunk's globals (overlaps with mma below) ----
        if (kc + 1 < KCHN) { loadA(kc + 1); loadB(kc + 1); }

        // ---- mma mainloop: 2 k16 steps ----
#pragma unroll
        for (int ks = 0; ks < 2; ks++) {
            uint32_t ah[2][4], al[2][4];
#pragma unroll
            for (int mf = 0; mf < 2; mf++) {
                uint32_t off = (uint32_t)(((aRow + mf * 16) * LDS + ks * 16 + aK) * 2);
                ldmx4(ah[mf], aBaseH + off);
                ldmx4(al[mf], aBaseL + off);
            }
#pragma unroll
            for (int f2 = 0; f2 < 4; f2++) {
                uint32_t boff = (uint32_t)(((bRow + f2 * 16) * LDS + ks * 16 + bK) * 2);
                uint32_t bh[4], bl[4];
                ldmx4(bh, bBaseH + boff);
                ldmx4(bl, bBaseL + boff);
#pragma unroll
                for (int j = 0; j < 2; j++) {
                    int nf = f2 * 2 + j;
#pragma unroll
                    for (int mf = 0; mf < 2; mf++) {
                        mma16816(acc[mf][nf], ah[mf], bh[2*j], bh[2*j+1]);
                        mma16816(acc[mf][nf], ah[mf], bl[2*j], bl[2*j+1]);
                        mma16816(acc[mf][nf], al[mf], bh[2*j], bh[2*j+1]);
                    }
                }
            }
        }
    }

    if (COP == 0) {
#pragma unroll
        for (int mf = 0; mf < 2; mf++) {
            int r0 = wm * 32 + mf * 16 + (lane >> 2);
#pragma unroll
            for (int nf = 0; nf < 8; nf++) {
                int col = bn + wn * 64 + nf * 8 + (lane & 3) * 2;
                *(float2*)(C + (m0 + r0) * Ntot + col)     = make_float2(acc[mf][nf][0], acc[mf][nf][1]);
                *(float2*)(C + (m0 + r0 + 8) * Ntot + col) = make_float2(acc[mf][nf][2], acc[mf][nf][3]);
            }
        }
    } else {
        // fused sigmoid + sf_fusion masked reduction over tokens -> C[b, bn:bn+128]
        int len = lens[b];
        float p[16];
#pragma unroll
        for (int i = 0; i < 16; i++) p[i] = 0.f;
#pragma unroll
        for (int nf = 0; nf < 8; nf++) {
            int hcol = bn + wn * 64 + nf * 8 + (lane & 3) * 2;
            float2 yv = *(const float2*)(xc + (size_t)b * HID + hcol);
            float ty0 = ftanh(yv.x), ty1 = ftanh(yv.y);
#pragma unroll
            for (int mf = 0; mf < 2; mf++) {
#pragma unroll
                for (int rh = 0; rh < 2; rh++) {
                    int l = wm * 32 + mf * 16 + (lane >> 2) + rh * 8;
                    if (l < len) {
                        float2 cv = *(const float2*)(xb + (m0 + l) * HID + hcol);
                        float f0 = fsig(acc[mf][nf][rh*2]);
                        float f1 = fsig(acc[mf][nf][rh*2+1]);
                        float o0 = 1.f - f0, o1 = 1.f - f1;
                        p[nf*2]   += f0 * (f0 * ftanh(cv.x) + cv.x) + o0 * (o0 * ty0 + yv.x);
                        p[nf*2+1] += f1 * (f1 * ftanh(cv.y) + cv.y) + o1 * (o1 * ty1 + yv.y);
                    }
                }
            }
        }
#pragma unroll
        for (int i = 0; i < 16; i++) {
            p[i] += __shfl_xor_sync(0xffffffffu, p[i], 4);
            p[i] += __shfl_xor_sync(0xffffffffu, p[i], 8);
            p[i] += __shfl_xor_sync(0xffffffffu, p[i], 16);
        }
        float* red = (float*)tiles[0];      // reuse tile smem (all reads done)
        __syncthreads();
        if (lane < 4) {
#pragma unroll
            for (int nf = 0; nf < 8; nf++) {
                red[wm * 128 + wn * 64 + nf * 8 + lane * 2]     = p[nf*2];
                red[wm * 128 + wn * 64 + nf * 8 + lane * 2 + 1] = p[nf*2+1];
            }
        }
        __syncthreads();
        if (tid < 128)
            C[(size_t)b * HID + bn + tid] = red[tid] + red[128 + tid] + red[256 + tid] + red[384 + tid];
    }
}

// ---------------- weight pre-split (transpose + bf16 hi/lo) ----------------
__global__ void k_wconv(const float* __restrict__ W, __nv_bfloat16* __restrict__ hi,
                        __nv_bfloat16* __restrict__ lo, int Kd, int Nd) {
    int idx = blockIdx.x * 256 + threadIdx.x;
    if (idx >= Kd * Nd) return;
    int n = idx / Kd, k = idx % Kd;          // output [N][K]
    float v = W[(size_t)k * Nd + n];
    __nv_bfloat16 h = __float2bfloat16(v);
    hi[idx] = h;
    lo[idx] = __float2bfloat16(v - __bfloat162float(h));
}

// ---------------- SIMT GEMM for the small [512,384,384] cases ----------------
enum { AOP_ID = 0, AOP_TANH = 1 };
template <int BM, int BN, int BK, int TM, int TN, int AOP>
__global__ void __launch_bounds__((BM / TM) * (BN / TN))
gemm_small(const float* __restrict__ A, const float* __restrict__ Bm,
           float* __restrict__ C, int M, int N, int K) {
    constexpr int THREADS = (BM / TM) * (BN / TN);
    constexpr int AV = BK / 4, ALOADS = (BM * AV) / THREADS, ARSTEP = THREADS / AV;
    constexpr int BV = BN / 4, BLOADS = (BK * BV) / THREADS, BRSTEP = THREADS / BV;
    __shared__ __align__(16) float As[BK][BM];
    __shared__ __align__(16) float Bs[BK][BN];
    int tid = threadIdx.x, bm = blockIdx.y * BM, bn = blockIdx.x * BN;
    int trow = tid / (BN / TN), tcol = tid % (BN / TN);
    int ar = tid / AV, ac = (tid % AV) * 4;
    int br = tid / BV, bc = (tid % BV) * 4;

    auto fetchA = [&](int row, int k) -> float4 {
        float4 v = *(const float4*)&A[(size_t)row * K + k];
        if (AOP == AOP_TANH) { v.x=ftanh(v.x); v.y=ftanh(v.y); v.z=ftanh(v.z); v.w=ftanh(v.w); }
        return v;
    };
    float4 aReg[ALOADS], bReg[BLOADS];
#pragma unroll
    for (int i = 0; i < ALOADS; i++) aReg[i] = fetchA(bm + ar + i * ARSTEP, ac);
#pragma unroll
    for (int i = 0; i < BLOADS; i++) bReg[i] = *(const float4*)&Bm[(size_t)(br + i * BRSTEP) * N + bn + bc];
    float acc[TM][TN] = {};
    for (int k0 = 0; k0 < K; k0 += BK) {
#pragma unroll
        for (int i = 0; i < ALOADS; i++) {
            int r = ar + i * ARSTEP;
            As[ac+0][r]=aReg[i].x; As[ac+1][r]=aReg[i].y; As[ac+2][r]=aReg[i].z; As[ac+3][r]=aReg[i].w;
        }
#pragma unroll
        for (int i = 0; i < BLOADS; i++) *(float4*)&Bs[br + i * BRSTEP][bc] = bReg[i];
        __syncthreads();
        int k1 = k0 + BK;
        if (k1 < K) {
#pragma unroll
            for (int i = 0; i < ALOADS; i++) aReg[i] = fetchA(bm + ar + i * ARSTEP, k1 + ac);
#pragma unroll
            for (int i = 0; i < BLOADS; i++) bReg[i] = *(const float4*)&Bm[(size_t)(k1 + br + i * BRSTEP) * N + bn + bc];
        }
#pragma unroll
        for (int kk = 0; kk < BK; kk++) {
            float ra[TM], rb[TN];
#pragma unroll
            for (int i = 0; i < TM; i += 4) *(float4*)&ra[i] = *(const float4*)&As[kk][trow * TM + i];
#pragma unroll
            for (int j = 0; j < TN; j += 4) *(float4*)&rb[j] = *(const float4*)&Bs[kk][tcol * TN + j];
#pragma unroll
            for (int i = 0; i < TM; i++)
#pragma unroll
                for (int j = 0; j < TN; j++) acc[i][j] = fmaf(ra[i], rb[j], acc[i][j]);
        }
        __syncthreads();
    }
#pragma unroll
    for (int i = 0; i < TM; i++) {
        int row = bm + trow * TM + i;
#pragma unroll
        for (int j = 0; j < TN; j += 4)
            *(float4*)&C[(size_t)row * N + bn + tcol * TN + j] =
                make_float4(acc[i][j], acc[i][j+1], acc[i][j+2], acc[i][j+3]);
    }
}

// ---------------- small kernels ----------------
__global__ void k_prep(const float* __restrict__ W3, const float* __restrict__ W4,
                       const float* __restrict__ b4, const float* __restrict__ W5) {
    int t = threadIdx.x;
    float v3 = 0.f, v4 = 0.f;
    for (int j = 0; j < HID; j++) {
        float w5 = W5[j];
        v3 += W3[t * HID + j] * w5;
        v4 += W4[t * HID + j] * w5;
    }
    g_w3v[t] = v3; g_w4v[t] = v4;
    if (t == 0) {
        float s = 0.f;
        for (int j = 0; j < HID; j++) s += b4[j] * W5[j];
        g_b4v = s;
    }
}

__global__ void k_hdot(const float* __restrict__ H) {
    int row = blockIdx.x * 8 + (threadIdx.x >> 5);
    int lane = threadIdx.x & 31;
    const float* hp = H + (size_t)row * HID;
    float v = 0.f;
    for (int h = lane; h < HID; h += 32) v += hp[h] * g_w4v[h];
#pragma unroll
    for (int o = 16; o > 0; o >>= 1) v += __shfl_down_sync(0xffffffffu, v, o);
    if (lane == 0) g_hdot[row] = v + g_b4v;
}

__global__ void k_idfuse(const float* __restrict__ Cs, const float* __restrict__ H,
                         const float* __restrict__ c_inte, const int* __restrict__ lens) {
    __shared__ float sr[LL];
    __shared__ float red[128];
    __shared__ float sal[LL];
    int b = blockIdx.x, t = threadIdx.x;
    int lane = t & 31, w = t >> 5;
    int len = lens[b];
    for (int l = w; l < LL; l += 12) {
        if (l < len) {
            const float* cp = Cs + ((size_t)b * LL + l) * HID;
            float v = 0.f;
            for (int hh = lane; hh < HID; hh += 32)
                v += g_g[b * HID + hh] * g_w3v[hh] * cp[hh];
#pragma unroll
            for (int o = 16; o > 0; o >>= 1) v += __shfl_down_sync(0xffffffffu, v, o);
            if (lane == 0) sr[l] = v + g_hdot[b * LL + l];
        } else if (lane == 0) sr[l] = -FLT_MAX;
    }
    __syncthreads();
    float rv = (t < 128) ? sr[t] : -FLT_MAX;
    if (t < 128) red[t] = rv;
    __syncthreads();
    for (int s = 64; s > 0; s >>= 1) { if (t < s) red[t] = fmaxf(red[t], red[t + s]); __syncthreads(); }
    float m = red[0];
    __syncthreads();
    float e = (t < 128) ? __expf(rv - m) : 0.f;
    if (t < 128) red[t] = e;
    __syncthreads();
    for (int s = 64; s > 0; s >>= 1) { if (t < s) red[t] += red[t + s]; __syncthreads(); }
    float sinv = __fdividef(1.0f, red[0]);
    if (t < 128) sal[t] = e * sinv;
    __syncthreads();
    int h = t;
    float gh = g_g[b * HID + h];
    const float* cp = Cs + (size_t)b * LL * HID + h;
    const float* hp = H + (size_t)b * LL * HID + h;
    float acc = 0.f;
    for (int l = 0; l < len; l++) {
        float a = sal[l];
        float cv = cp[(size_t)l * HID];
        float Hv = hp[(size_t)l * HID];
        float x = gh * cv;
        float oma = 1.0f - a;
        acc += a * (a * ftanh(x) + x) + oma * (oma * ftanh(Hv) + Hv);
    }
    g_rin[b * HID + h] = acc + c_inte[b * HID + h];
}

__global__ void k_intent(const float* __restrict__ Wi, float* __restrict__ out) {
    int n = threadIdx.x;
    int b = blockIdx.x * blockDim.y + threadIdx.y;
    float v = 0.f;
    for (int k = 0; k < HID; k++) v += g_rin[b * HID + k] * Wi[k * NLAB + n];
    out[b * NLAB + n] = v;
}

// ---------------- launch ----------------
extern "C" void kernel_launch(void* const* d_in, const int* in_sizes, int n_in,
                              void* d_out, int out_size) {
    const float* H      = (const float*)d_in[0];
    const float* Cs     = (const float*)d_in[1];
    const float* c_inte = (const float*)d_in[2];
    const float* W0     = (const float*)d_in[3];
    const float* W1     = (const float*)d_in[4];
    const float* W2     = (const float*)d_in[5];
    const float* W3     = (const float*)d_in[6];
    const float* W4     = (const float*)d_in[7];
    const float* b4     = (const float*)d_in[8];
    const float* W5     = (const float*)d_in[9];
    const float* V_SF   = (const float*)d_in[10];
    const float* W_inte = (const float*)d_in[11];
    const float* W_slot = (const float*)d_in[12];
    const int*   lens   = (const int*)d_in[13];
    float* out = (float*)d_out;

    float *pT0, *pS, *pY1, *pG, *pRin;
    __nv_bfloat16 *pW0h, *pW0l, *pW2h, *pW2l, *pWsh, *pWsl;
    cudaGetSymbolAddress((void**)&pT0,  g_T0);
    cudaGetSymbolAddress((void**)&pS,   g_S);
    cudaGetSymbolAddress((void**)&pY1,  g_y1);
    cudaGetSymbolAddress((void**)&pG,   g_g);
    cudaGetSymbolAddress((void**)&pRin, g_rin);
    cudaGetSymbolAddress((void**)&pW0h, g_W0h); cudaGetSymbolAddress((void**)&pW0l, g_W0l);
    cudaGetSymbolAddress((void**)&pW2h, g_W2h); cudaGetSymbolAddress((void**)&pW2l, g_W2l);
    cudaGetSymbolAddress((void**)&pWsh, g_Wsh); cudaGetSymbolAddress((void**)&pWsl, g_Wsl);

    // precompute (iteration-invariant)
    k_prep<<<1, HID>>>(W3, W4, b4, W5);
    k_hdot<<<NROWS / 8, 256>>>(H);
    k_wconv<<<(HID * HID + 255) / 256, 256>>>(W0, pW0h, pW0l, HID, HID);
    k_wconv<<<(HID * HID + 255) / 256, 256>>>(W2, pW2h, pW2l, HID, HID);
    k_wconv<<<(2 * HID * NSLOT + 255) / 256, 256>>>(W_slot, pWsh, pWsl, 2 * HID, NSLOT);
    // T0 = tanh(Cs) @ W0
    wmma_big<12, MAOP_TANH, 0><<<dim3(HID / 128, BB), 256>>>(
        Cs, pW0h, pW0l, pT0, HID, nullptr, nullptr, nullptr, nullptr);
    cudaMemcpyAsync(pRin, c_inte, (size_t)BB * HID * sizeof(float), cudaMemcpyDeviceToDevice);

    for (int it = 0; it < ITERS; ++it) {
        // y1 = tanh(r_inte) @ W1
        gemm_small<64, 64, 16, 4, 4, AOP_TANH>
            <<<dim3(HID / 64, BB / 64), 256>>>(pRin, W1, pY1, BB, HID, HID);
        // S[b,:] = sum_l sf_fusion(sigmoid(tanh(T0 + y1[b]) @ W2), ...) — tensor-core + fused reduce
        wmma_big<12, MAOP_T0Y1, 1><<<dim3(HID / 128, BB), 256>>>(
            pT0, pW2h, pW2l, pS, HID, pY1, Cs, pRin, lens);
        // g = S @ V_SF
        gemm_small<64, 64, 16, 4, 4, AOP_ID>
            <<<dim3(HID / 64, BB / 64), 256>>>(pS, V_SF, pG, BB, HID, HID);
        k_idfuse<<<BB, HID>>>(Cs, H, c_inte, lens);
    }

    k_intent<<<BB / 8, dim3(NLAB, 8)>>>(W_inte, out);
    // slot_output = [H | g (x) c] @ W_slot — tensor-core, concat in prologue
    wmma_big<24, MAOP_CONCAT, 0><<<dim3(NSLOT / 128, BB), 256>>>(
        H, pWsh, pWsl, out + BB * NLAB, NSLOT, Cs, pG, nullptr, nullptr);
}

// round 12
// speedup vs baseline: 1.3144x; 1.3144x over previous
#include <cuda_runtime.h>
#include <cuda_bf16.h>
#include <cfloat>
#include <cstdint>

// Problem constants
#define BB 512
#define LL 128
#define HID 384
#define NLAB 32
#define NSLOT 128
#define NROWS (BB*LL)          // 65536
#define ITERS 3

// ---------------- scratch (static device allocations) ----------------
__device__ float g_T0[NROWS*HID];       // tanh(c) @ W0 (iteration-invariant)
__device__ float g_S [BB*HID];
__device__ float g_y1[BB*HID];
__device__ float g_g [BB*HID];
__device__ float g_rin[BB*HID];
__device__ float g_w3v[HID];
__device__ float g_w4v[HID];
__device__ float g_b4v;
__device__ float g_hdot[NROWS];
// pre-split weights, [N rows][K cols] (K contiguous == col-major B for mma row.col)
__device__ __nv_bfloat16 g_W0h[HID*HID],  g_W0l[HID*HID];
__device__ __nv_bfloat16 g_W2h[HID*HID],  g_W2l[HID*HID];
__device__ __nv_bfloat16 g_Wsh[NSLOT*2*HID], g_Wsl[NSLOT*2*HID];

// ---------------- fast math ----------------
__device__ __forceinline__ float ftanh(float x) {
    float e = __expf(2.0f * x);
    return 1.0f - __fdividef(2.0f, e + 1.0f);
}
__device__ __forceinline__ float fsig(float x) {
    return __fdividef(1.0f, 1.0f + __expf(-x));
}

// ---------------- base-ISA tensor core helpers ----------------
__device__ __forceinline__ uint32_t smem_u32(const void* p) {
    uint32_t a;
    asm("{ .reg .u64 t; cvta.to.shared.u64 t, %1; cvt.u32.u64 %0, t; }" : "=r"(a) : "l"(p));
    return a;
}
__device__ __forceinline__ void ldmx4(uint32_t* r, uint32_t addr) {
    asm volatile("ldmatrix.sync.aligned.m8n8.x4.shared.b16 {%0,%1,%2,%3}, [%4];"
        : "=r"(r[0]), "=r"(r[1]), "=r"(r[2]), "=r"(r[3]) : "r"(addr));
}
__device__ __forceinline__ void mma16816(float* d, const uint32_t* a,
                                         uint32_t b0, uint32_t b1) {
    asm volatile("mma.sync.aligned.m16n8k16.row.col.f32.bf16.bf16.f32 "
        "{%0,%1,%2,%3}, {%4,%5,%6,%7}, {%8,%9}, {%0,%1,%2,%3};"
        : "+f"(d[0]), "+f"(d[1]), "+f"(d[2]), "+f"(d[3])
        : "r"(a[0]), "r"(a[1]), "r"(a[2]), "r"(a[3]), "r"(b0), "r"(b1));
}

// ---------------- big tensor-core GEMM (static smem, BK=32, A-only prefetch) ------
// C[128 rows, 128 cols per CTA] = prologue(A)[128, K] @ B^T, K = KCHN*32.
// grid = (Ntot/128, BB).  8 warps = 4(m) x 2(n); warp tile 32x64.
// AOP: 1=tanh(A)  2=tanh(A + y[b])  3=concat(A=H | A2 * g[b])
// COP: 0=store fp32   1=sigmoid + masked sf-reduction -> C[b, HID] slice
enum { MAOP_TANH = 1, MAOP_T0Y1 = 2, MAOP_CONCAT = 3 };

template <int KCHN, int AOP, int COP>
__global__ void __launch_bounds__(256, 2)
wmma_big(const float* __restrict__ A, const __nv_bfloat16* __restrict__ Bhi,
         const __nv_bfloat16* __restrict__ Blo, float* __restrict__ C, int Ntot,
         const float* __restrict__ xa, const float* __restrict__ xb,
         const float* __restrict__ xc, const int* __restrict__ lens) {
    constexpr int K = KCHN * 32;
    constexpr int LDS = 40;                 // bf16 per smem row (32 + 8 pad -> 80B stride)
    __shared__ __align__(16) __nv_bfloat16 tiles[4][128 * LDS];   // 40960 B
    __shared__ float sy[HID];               // per-b broadcast vector cache
    __nv_bfloat16* sAh = tiles[0];
    __nv_bfloat16* sAl = tiles[1];
    __nv_bfloat16* sBh = tiles[2];
    __nv_bfloat16* sBl = tiles[3];

    int tid = threadIdx.x, lane = tid & 31, wid = tid >> 5;
    int wm = wid & 3, wn = wid >> 2;
    int b = blockIdx.y;
    int bn = blockIdx.x * 128;
    size_t m0 = (size_t)b * 128;

    // cache per-b vector (y1 row for T0Y1, g row for CONCAT)
    if (AOP == MAOP_T0Y1) {
        if (tid < 128) { sy[tid] = xa[(size_t)b * HID + tid];
                         sy[tid + 128] = xa[(size_t)b * HID + tid + 128];
                         sy[tid + 256] = xa[(size_t)b * HID + tid + 256]; }
    } else if (AOP == MAOP_CONCAT) {
        if (tid < 128) { sy[tid] = xb[(size_t)b * HID + tid];
                         sy[tid + 128] = xb[(size_t)b * HID + tid + 128];
                         sy[tid + 256] = xb[(size_t)b * HID + tid + 256]; }
    }

    float acc[2][8][4];
#pragma unroll
    for (int mf = 0; mf < 2; mf++)
#pragma unroll
        for (int nf = 0; nf < 8; nf++)
#pragma unroll
            for (int e = 0; e < 4; e++) acc[mf][nf][e] = 0.f;

    uint32_t aBaseH = smem_u32(sAh), aBaseL = smem_u32(sAl);
    uint32_t bBaseH = smem_u32(sBh), bBaseL = smem_u32(sBl);
    int aRow = wm * 32 + (lane & 15);
    int aK   = (lane & 16) >> 1;                              // 0 / 8
    int bRow = wn * 64 + ((lane & 16) >> 1) + (lane & 7);
    int bK   = lane & 8;

    // per-thread tile coordinates (2 iters per chunk)
    int arow0 = tid >> 2, ag8_0 = tid & 3;                    // it=0
    int arow1 = (tid + 256) >> 2, ag8_1 = (tid + 256) & 3;    // it=1

    // ---- A-only raw global prefetch (DRAM-latency path) ----
    float pA[2][8];
    auto loadA = [&](int kc) {
#pragma unroll
        for (int it = 0; it < 2; it++) {
            int row = it ? arow1 : arow0;
            int g8  = it ? ag8_1 : ag8_0;
            int gk  = kc * 32 + g8 * 8;
            const float4* p;
            if (AOP == MAOP_CONCAT && gk >= HID)
                p = (const float4*)(xa + (m0 + row) * HID + (gk - HID));
            else
                p = (const float4*)(A + (m0 + row) * HID + gk);
            float4 a0 = p[0], a1 = p[1];
            pA[it][0]=a0.x; pA[it][1]=a0.y; pA[it][2]=a0.z; pA[it][3]=a0.w;
            pA[it][4]=a1.x; pA[it][5]=a1.y; pA[it][6]=a1.z; pA[it][7]=a1.w;
        }
    };

    const uint4* bhp = (const uint4*)Bhi;
    const uint4* blp = (const uint4*)Blo;

    loadA(0);
    __syncthreads();          // sy visible before first STS reads it

    for (int kc = 0; kc < KCHN; kc++) {
        if (kc) __syncthreads();          // prior chunk's ldmatrix done before overwrite
        // ---- B load (L2-resident; synchronous) + STS of prologued A ----
#pragma unroll
        for (int it = 0; it < 2; it++) {
            int row = it ? arow1 : arow0;
            int g8  = it ? ag8_1 : ag8_0;
            int gk  = kc * 32 + g8 * 8;
            size_t gi = ((size_t)(bn + row) * K + kc * 32 + g8 * 8) >> 3;
            uint4 bhv = bhp[gi];
            uint4 blv = blp[gi];
            float v[8];
            if (AOP == MAOP_TANH) {
#pragma unroll
                for (int q = 0; q < 8; q++) v[q] = ftanh(pA[it][q]);
            } else if (AOP == MAOP_T0Y1) {
#pragma unroll
                for (int q = 0; q < 8; q++) v[q] = ftanh(pA[it][q] + sy[gk + q]);
            } else { // MAOP_CONCAT
                if (gk < HID) {
#pragma unroll
                    for (int q = 0; q < 8; q++) v[q] = pA[it][q];
                } else {
                    int k2 = gk - HID;
#pragma unroll
                    for (int q = 0; q < 8; q++) v[q] = pA[it][q] * sy[k2 + q];
                }
            }
            uint4 hu, lu;
            uint32_t* hw = (uint32_t*)&hu;
            uint32_t* lw = (uint32_t*)&lu;
#pragma unroll
            for (int q = 0; q < 4; q++) {
                __nv_bfloat16 h0 = __float2bfloat16(v[2*q]);
                __nv_bfloat16 h1 = __float2bfloat16(v[2*q+1]);
                float l0 = v[2*q]   - __bfloat162float(h0);
                float l1 = v[2*q+1] - __bfloat162float(h1);
                __nv_bfloat16 e0 = __float2bfloat16(l0), e1 = __float2bfloat16(l1);
                hw[q] = (uint32_t)__bfloat16_as_ushort(h0) | ((uint32_t)__bfloat16_as_ushort(h1) << 16);
                lw[q] = (uint32_t)__bfloat16_as_ushort(e0) | ((uint32_t)__bfloat16_as_ushort(e1) << 16);
            }
            *(uint4*)(sAh + row * LDS + g8 * 8) = hu;
            *(uint4*)(sAl + row * LDS + g8 * 8) = lu;
            *(uint4*)(sBh + row * LDS + g8 * 8) = bhv;
            *(uint4*)(sBl + row * LDS + g8 * 8) = blv;
        }
        __syncthreads();

        // ---- prefetch next chunk's A (overlaps with mma below) ----
        if (kc + 1 < KCHN) loadA(kc + 1);

        // ---- mma mainloop: 2 k16 steps ----
#pragma unroll
        for (int ks = 0; ks < 2; ks++) {
            uint32_t ah[2][4], al[2][4];
#pragma unroll
            for (int mf = 0; mf < 2; mf++) {
                uint32_t off = (uint32_t)(((aRow + mf * 16) * LDS + ks * 16 + aK) * 2);
                ldmx4(ah[mf], aBaseH + off);
                ldmx4(al[mf], aBaseL + off);
            }
#pragma unroll
            for (int f2 = 0; f2 < 4; f2++) {
                uint32_t boff = (uint32_t)(((bRow + f2 * 16) * LDS + ks * 16 + bK) * 2);
                uint32_t bh[4], bl[4];
                ldmx4(bh, bBaseH + boff);
                ldmx4(bl, bBaseL + boff);
#pragma unroll
                for (int j = 0; j < 2; j++) {
                    int nf = f2 * 2 + j;
#pragma unroll
                    for (int mf = 0; mf < 2; mf++) {
                        mma16816(acc[mf][nf], ah[mf], bh[2*j], bh[2*j+1]);
                        mma16816(acc[mf][nf], ah[mf], bl[2*j], bl[2*j+1]);
                        mma16816(acc[mf][nf], al[mf], bh[2*j], bh[2*j+1]);
                    }
                }
            }
        }
    }

    if (COP == 0) {
#pragma unroll
        for (int mf = 0; mf < 2; mf++) {
            int r0 = wm * 32 + mf * 16 + (lane >> 2);
#pragma unroll
            for (int nf = 0; nf < 8; nf++) {
                int col = bn + wn * 64 + nf * 8 + (lane & 3) * 2;
                *(float2*)(C + (m0 + r0) * Ntot + col)     = make_float2(acc[mf][nf][0], acc[mf][nf][1]);
                *(float2*)(C + (m0 + r0 + 8) * Ntot + col) = make_float2(acc[mf][nf][2], acc[mf][nf][3]);
            }
        }
    } else {
        // fused sigmoid + sf_fusion masked reduction over tokens -> C[b, bn:bn+128]
        int len = lens[b];
        float p[16];
#pragma unroll
        for (int i = 0; i < 16; i++) p[i] = 0.f;
#pragma unroll
        for (int nf = 0; nf < 8; nf++) {
            int hcol = bn + wn * 64 + nf * 8 + (lane & 3) * 2;
            float2 yv = *(const float2*)(xc + (size_t)b * HID + hcol);
            float ty0 = ftanh(yv.x), ty1 = ftanh(yv.y);
#pragma unroll
            for (int mf = 0; mf < 2; mf++) {
#pragma unroll
                for (int rh = 0; rh < 2; rh++) {
                    int l = wm * 32 + mf * 16 + (lane >> 2) + rh * 8;
                    if (l < len) {
                        float2 cv = *(const float2*)(xb + (m0 + l) * HID + hcol);
                        float f0 = fsig(acc[mf][nf][rh*2]);
                        float f1 = fsig(acc[mf][nf][rh*2+1]);
                        float o0 = 1.f - f0, o1 = 1.f - f1;
                        p[nf*2]   += f0 * (f0 * ftanh(cv.x) + cv.x) + o0 * (o0 * ty0 + yv.x);
                        p[nf*2+1] += f1 * (f1 * ftanh(cv.y) + cv.y) + o1 * (o1 * ty1 + yv.y);
                    }
                }
            }
        }
#pragma unroll
        for (int i = 0; i < 16; i++) {
            p[i] += __shfl_xor_sync(0xffffffffu, p[i], 4);
            p[i] += __shfl_xor_sync(0xffffffffu, p[i], 8);
            p[i] += __shfl_xor_sync(0xffffffffu, p[i], 16);
        }
        float* red = (float*)tiles[0];      // reuse tile smem (all reads done)
        __syncthreads();
        if (lane < 4) {
#pragma unroll
            for (int nf = 0; nf < 8; nf++) {
                red[wm * 128 + wn * 64 + nf * 8 + lane * 2]     = p[nf*2];
                red[wm * 128 + wn * 64 + nf * 8 + lane * 2 + 1] = p[nf*2+1];
            }
        }
        __syncthreads();
        if (tid < 128)
            C[(size_t)b * HID + bn + tid] = red[tid] + red[128 + tid] + red[256 + tid] + red[384 + tid];
    }
}

// ---------------- weight pre-split (transpose + bf16 hi/lo) ----------------
__global__ void k_wconv(const float* __restrict__ W, __nv_bfloat16* __restrict__ hi,
                        __nv_bfloat16* __restrict__ lo, int Kd, int Nd) {
    int idx = blockIdx.x * 256 + threadIdx.x;
    if (idx >= Kd * Nd) return;
    int n = idx / Kd, k = idx % Kd;          // output [N][K]
    float v = W[(size_t)k * Nd + n];
    __nv_bfloat16 h = __float2bfloat16(v);
    hi[idx] = h;
    lo[idx] = __float2bfloat16(v - __bfloat162float(h));
}

// ---------------- SIMT GEMM for the small [512,384,384] cases ----------------
enum { AOP_ID = 0, AOP_TANH = 1 };
template <int BM, int BN, int BK, int TM, int TN, int AOP>
__global__ void __launch_bounds__((BM / TM) * (BN / TN))
gemm_small(const float* __restrict__ A, const float* __restrict__ Bm,
           float* __restrict__ C, int M, int N, int K) {
    constexpr int THREADS = (BM / TM) * (BN / TN);
    constexpr int AV = BK / 4, ALOADS = (BM * AV) / THREADS, BRSTEP0 = THREADS / AV;
    constexpr int ARSTEP = THREADS / AV;
    constexpr int BV = BN / 4, BLOADS = (BK * BV) / THREADS, BRSTEP = THREADS / BV;
    __shared__ __align__(16) float As[BK][BM];
    __shared__ __align__(16) float Bs[BK][BN];
    int tid = threadIdx.x, bm = blockIdx.y * BM, bn = blockIdx.x * BN;
    int trow = tid / (BN / TN), tcol = tid % (BN / TN);
    int ar = tid / AV, ac = (tid % AV) * 4;
    int br = tid / BV, bc = (tid % BV) * 4;
    (void)BRSTEP0;

    auto fetchA = [&](int row, int k) -> float4 {
        float4 v = *(const float4*)&A[(size_t)row * K + k];
        if (AOP == AOP_TANH) { v.x=ftanh(v.x); v.y=ftanh(v.y); v.z=ftanh(v.z); v.w=ftanh(v.w); }
        return v;
    };
    float4 aReg[ALOADS], bReg[BLOADS];
#pragma unroll
    for (int i = 0; i < ALOADS; i++) aReg[i] = fetchA(bm + ar + i * ARSTEP, ac);
#pragma unroll
    for (int i = 0; i < BLOADS; i++) bReg[i] = *(const float4*)&Bm[(size_t)(br + i * BRSTEP) * N + bn + bc];
    float acc[TM][TN] = {};
    for (int k0 = 0; k0 < K; k0 += BK) {
#pragma unroll
        for (int i = 0; i < ALOADS; i++) {
            int r = ar + i * ARSTEP;
            As[ac+0][r]=aReg[i].x; As[ac+1][r]=aReg[i].y; As[ac+2][r]=aReg[i].z; As[ac+3][r]=aReg[i].w;
        }
#pragma unroll
        for (int i = 0; i < BLOADS; i++) *(float4*)&Bs[br + i * BRSTEP][bc] = bReg[i];
        __syncthreads();
        int k1 = k0 + BK;
        if (k1 < K) {
#pragma unroll
            for (int i = 0; i < ALOADS; i++) aReg[i] = fetchA(bm + ar + i * ARSTEP, k1 + ac);
#pragma unroll
            for (int i = 0; i < BLOADS; i++) bReg[i] = *(const float4*)&Bm[(size_t)(k1 + br + i * BRSTEP) * N + bn + bc];
        }
#pragma unroll
        for (int kk = 0; kk < BK; kk++) {
            float ra[TM], rb[TN];
#pragma unroll
            for (int i = 0; i < TM; i += 4) *(float4*)&ra[i] = *(const float4*)&As[kk][trow * TM + i];
#pragma unroll
            for (int j = 0; j < TN; j += 4) *(float4*)&rb[j] = *(const float4*)&Bs[kk][tcol * TN + j];
#pragma unroll
            for (int i = 0; i < TM; i++)
#pragma unroll
                for (int j = 0; j < TN; j++) acc[i][j] = fmaf(ra[i], rb[j], acc[i][j]);
        }
        __syncthreads();
    }
#pragma unroll
    for (int i = 0; i < TM; i++) {
        int row = bm + trow * TM + i;
#pragma unroll
        for (int j = 0; j < TN; j += 4)
            *(float4*)&C[(size_t)row * N + bn + tcol * TN + j] =
                make_float4(acc[i][j], acc[i][j+1], acc[i][j+2], acc[i][j+3]);
    }
}

// ---------------- small kernels ----------------
__global__ void k_prep(const float* __restrict__ W3, const float* __restrict__ W4,
                       const float* __restrict__ b4, const float* __restrict__ W5) {
    int t = threadIdx.x;
    float v3 = 0.f, v4 = 0.f;
    for (int j = 0; j < HID; j++) {
        float w5 = W5[j];
        v3 += W3[t * HID + j] * w5;
        v4 += W4[t * HID + j] * w5;
    }
    g_w3v[t] = v3; g_w4v[t] = v4;
    if (t == 0) {
        float s = 0.f;
        for (int j = 0; j < HID; j++) s += b4[j] * W5[j];
        g_b4v = s;
    }
}

__global__ void k_hdot(const float* __restrict__ H) {
    int row = blockIdx.x * 8 + (threadIdx.x >> 5);
    int lane = threadIdx.x & 31;
    const float* hp = H + (size_t)row * HID;
    float v = 0.f;
    for (int h = lane; h < HID; h += 32) v += hp[h] * g_w4v[h];
#pragma unroll
    for (int o = 16; o > 0; o >>= 1) v += __shfl_down_sync(0xffffffffu, v, o);
    if (lane == 0) g_hdot[row] = v + g_b4v;
}

__global__ void k_idfuse(const float* __restrict__ Cs, const float* __restrict__ H,
                         const float* __restrict__ c_inte, const int* __restrict__ lens) {
    __shared__ float sr[LL];
    __shared__ float red[128];
    __shared__ float sal[LL];
    int b = blockIdx.x, t = threadIdx.x;
    int lane = t & 31, w = t >> 5;
    int len = lens[b];
    for (int l = w; l < LL; l += 12) {
        if (l < len) {
            const float* cp = Cs + ((size_t)b * LL + l) * HID;
            float v = 0.f;
            for (int hh = lane; hh < HID; hh += 32)
                v += g_g[b * HID + hh] * g_w3v[hh] * cp[hh];
#pragma unroll
            for (int o = 16; o > 0; o >>= 1) v += __shfl_down_sync(0xffffffffu, v, o);
            if (lane == 0) sr[l] = v + g_hdot[b * LL + l];
        } else if (lane == 0) sr[l] = -FLT_MAX;
    }
    __syncthreads();
    float rv = (t < 128) ? sr[t] : -FLT_MAX;
    if (t < 128) red[t] = rv;
    __syncthreads();
    for (int s = 64; s > 0; s >>= 1) { if (t < s) red[t] = fmaxf(red[t], red[t + s]); __syncthreads(); }
    float m = red[0];
    __syncthreads();
    float e = (t < 128) ? __expf(rv - m) : 0.f;
    if (t < 128) red[t] = e;
    __syncthreads();
    for (int s = 64; s > 0; s >>= 1) { if (t < s) red[t] += red[t + s]; __syncthreads(); }
    float sinv = __fdividef(1.0f, red[0]);
    if (t < 128) sal[t] = e * sinv;
    __syncthreads();
    int h = t;
    float gh = g_g[b * HID + h];
    const float* cp = Cs + (size_t)b * LL * HID + h;
    const float* hp = H + (size_t)b * LL * HID + h;
    float acc = 0.f;
    for (int l = 0; l < len; l++) {
        float a = sal[l];
        float cv = cp[(size_t)l * HID];
        float Hv = hp[(size_t)l * HID];
        float x = gh * cv;
        float oma = 1.0f - a;
        acc += a * (a * ftanh(x) + x) + oma * (oma * ftanh(Hv) + Hv);
    }
    g_rin[b * HID + h] = acc + c_inte[b * HID + h];
}

__global__ void k_intent(const float* __restrict__ Wi, float* __restrict__ out) {
    int n = threadIdx.x;
    int b = blockIdx.x * blockDim.y + threadIdx.y;
    float v = 0.f;
    for (int k = 0; k < HID; k++) v += g_rin[b * HID + k] * Wi[k * NLAB + n];
    out[b * NLAB + n] = v;
}

// ---------------- launch ----------------
extern "C" void kernel_launch(void* const* d_in, const int* in_sizes, int n_in,
                              void* d_out, int out_size) {
    const float* H      = (const float*)d_in[0];
    const float* Cs     = (const float*)d_in[1];
    const float* c_inte = (const float*)d_in[2];
    const float* W0     = (const float*)d_in[3];
    const float* W1     = (const float*)d_in[4];
    const float* W2     = (const float*)d_in[5];
    const float* W3     = (const float*)d_in[6];
    const float* W4     = (const float*)d_in[7];
    const float* b4     = (const float*)d_in[8];
    const float* W5     = (const float*)d_in[9];
    const float* V_SF   = (const float*)d_in[10];
    const float* W_inte = (const float*)d_in[11];
    const float* W_slot = (const float*)d_in[12];
    const int*   lens   = (const int*)d_in[13];
    float* out = (float*)d_out;

    float *pT0, *pS, *pY1, *pG, *pRin;
    __nv_bfloat16 *pW0h, *pW0l, *pW2h, *pW2l, *pWsh, *pWsl;
    cudaGetSymbolAddress((void**)&pT0,  g_T0);
    cudaGetSymbolAddress((void**)&pS,   g_S);
    cudaGetSymbolAddress((void**)&pY1,  g_y1);
    cudaGetSymbolAddress((void**)&pG,   g_g);
    cudaGetSymbolAddress((void**)&pRin, g_rin);
    cudaGetSymbolAddress((void**)&pW0h, g_W0h); cudaGetSymbolAddress((void**)&pW0l, g_W0l);
    cudaGetSymbolAddress((void**)&pW2h, g_W2h); cudaGetSymbolAddress((void**)&pW2l, g_W2l);
    cudaGetSymbolAddress((void**)&pWsh, g_Wsh); cudaGetSymbolAddress((void**)&pWsl, g_Wsl);

    // precompute (iteration-invariant)
    k_prep<<<1, HID>>>(W3, W4, b4, W5);
    k_hdot<<<NROWS / 8, 256>>>(H);
    k_wconv<<<(HID * HID + 255) / 256, 256>>>(W0, pW0h, pW0l, HID, HID);
    k_wconv<<<(HID * HID + 255) / 256, 256>>>(W2, pW2h, pW2l, HID, HID);
    k_wconv<<<(2 * HID * NSLOT + 255) / 256, 256>>>(W_slot, pWsh, pWsl, 2 * HID, NSLOT);
    // T0 = tanh(Cs) @ W0
    wmma_big<12, MAOP_TANH, 0><<<dim3(HID / 128, BB), 256>>>(
        Cs, pW0h, pW0l, pT0, HID, nullptr, nullptr, nullptr, nullptr);
    cudaMemcpyAsync(pRin, c_inte, (size_t)BB * HID * sizeof(float), cudaMemcpyDeviceToDevice);

    for (int it = 0; it < ITERS; ++it) {
        // y1 = tanh(r_inte) @ W1   (96 CTAs for better occupancy)
        gemm_small<32, 64, 16, 4, 4, AOP_TANH>
            <<<dim3(HID / 64, BB / 32), 128>>>(pRin, W1, pY1, BB, HID, HID);
        // S[b,:] = sum_l sf_fusion(sigmoid(tanh(T0 + y1[b]) @ W2), ...) — tensor-core + fused reduce
        wmma_big<12, MAOP_T0Y1, 1><<<dim3(HID / 128, BB), 256>>>(
            pT0, pW2h, pW2l, pS, HID, pY1, Cs, pRin, lens);
        // g = S @ V_SF
        gemm_small<32, 64, 16, 4, 4, AOP_ID>
            <<<dim3(HID / 64, BB / 32), 128>>>(pS, V_SF, pG, BB, HID, HID);
        k_idfuse<<<BB, HID>>>(Cs, H, c_inte, lens);
    }

    k_intent<<<BB / 8, dim3(NLAB, 8)>>>(W_inte, out);
    // slot_output = [H | g (x) c] @ W_slot — tensor-core, concat in prologue
    wmma_big<24, MAOP_CONCAT, 0><<<dim3(NSLOT / 128, BB), 256>>>(
        H, pWsh, pWsl, out + BB * NLAB, NSLOT, Cs, pG, nullptr, nullptr);
}

// round 13
// speedup vs baseline: 1.3598x; 1.0346x over previous
#include <cuda_runtime.h>
#include <cuda_bf16.h>
#include <cfloat>
#include <cstdint>

// Problem constants
#define BB 512
#define LL 128
#define HID 384
#define NLAB 32
#define NSLOT 128
#define NROWS (BB*LL)          // 65536
#define ITERS 3

// ---------------- scratch (static device allocations) ----------------
__device__ float g_T0[NROWS*HID];       // tanh(c) @ W0 (iteration-invariant)
__device__ float g_S [BB*HID];
__device__ float g_y1[BB*HID];
__device__ float g_g [BB*HID];
__device__ float g_rin[BB*HID];
__device__ float g_w3v[HID];
__device__ float g_w4v[HID];
__device__ float g_b4v;
__device__ float g_hdot[NROWS];
// pre-split weights, [N rows][K cols] (K contiguous == col-major B for mma row.col)
__device__ __nv_bfloat16 g_W0h[HID*HID],  g_W0l[HID*HID];
__device__ __nv_bfloat16 g_W2h[HID*HID],  g_W2l[HID*HID];
__device__ __nv_bfloat16 g_Wsh[NSLOT*2*HID], g_Wsl[NSLOT*2*HID];

// ---------------- fast math (HW MUFU.TANH) ----------------
__device__ __forceinline__ float ftanh(float x) {
    float r;
    asm("tanh.approx.f32 %0, %1;" : "=f"(r) : "f"(x));
    return r;
}
__device__ __forceinline__ float fsig(float x) {
    float r;
    asm("tanh.approx.f32 %0, %1;" : "=f"(r) : "f"(x * 0.5f));
    return fmaf(r, 0.5f, 0.5f);
}

// ---------------- base-ISA tensor core helpers ----------------
__device__ __forceinline__ uint32_t smem_u32(const void* p) {
    uint32_t a;
    asm("{ .reg .u64 t; cvta.to.shared.u64 t, %1; cvt.u32.u64 %0, t; }" : "=r"(a) : "l"(p));
    return a;
}
__device__ __forceinline__ void ldmx4(uint32_t* r, uint32_t addr) {
    asm volatile("ldmatrix.sync.aligned.m8n8.x4.shared.b16 {%0,%1,%2,%3}, [%4];"
        : "=r"(r[0]), "=r"(r[1]), "=r"(r[2]), "=r"(r[3]) : "r"(addr));
}
__device__ __forceinline__ void mma16816(float* d, const uint32_t* a,
                                         uint32_t b0, uint32_t b1) {
    asm volatile("mma.sync.aligned.m16n8k16.row.col.f32.bf16.bf16.f32 "
        "{%0,%1,%2,%3}, {%4,%5,%6,%7}, {%8,%9}, {%0,%1,%2,%3};"
        : "+f"(d[0]), "+f"(d[1]), "+f"(d[2]), "+f"(d[3])
        : "r"(a[0]), "r"(a[1]), "r"(a[2]), "r"(a[3]), "r"(b0), "r"(b1));
}

// ---------------- big tensor-core GEMM (static smem, BK=32, A-only prefetch) ------
// C[128 rows, 128 cols per CTA] = prologue(A)[128, K] @ B^T, K = KCHN*32.
// grid = (Ntot/128, BB).  8 warps = 4(m) x 2(n); warp tile 32x64.
// AOP: 1=tanh(A)  2=tanh(A + y[b])  3=concat(A=H | A2 * g[b])
// COP: 0=store fp32   1=sigmoid + masked sf-reduction -> C[b, HID] slice
enum { MAOP_TANH = 1, MAOP_T0Y1 = 2, MAOP_CONCAT = 3 };

template <int KCHN, int AOP, int COP>
__global__ void __launch_bounds__(256, 2)
wmma_big(const float* __restrict__ A, const __nv_bfloat16* __restrict__ Bhi,
         const __nv_bfloat16* __restrict__ Blo, float* __restrict__ C, int Ntot,
         const float* __restrict__ xa, const float* __restrict__ xb,
         const float* __restrict__ xc, const int* __restrict__ lens) {
    constexpr int K = KCHN * 32;
    constexpr int LDS = 40;                 // bf16 per smem row (32 + 8 pad -> 80B stride)
    __shared__ __align__(16) __nv_bfloat16 tiles[4][128 * LDS];   // 40960 B
    __shared__ float sy[HID];               // per-b broadcast vector cache
    __nv_bfloat16* sAh = tiles[0];
    __nv_bfloat16* sAl = tiles[1];
    __nv_bfloat16* sBh = tiles[2];
    __nv_bfloat16* sBl = tiles[3];

    int tid = threadIdx.x, lane = tid & 31, wid = tid >> 5;
    int wm = wid & 3, wn = wid >> 2;
    int b = blockIdx.y;
    int bn = blockIdx.x * 128;
    size_t m0 = (size_t)b * 128;

    // cache per-b vector (y1 row for T0Y1, g row for CONCAT)
    if (AOP == MAOP_T0Y1) {
        if (tid < 128) { sy[tid] = xa[(size_t)b * HID + tid];
                         sy[tid + 128] = xa[(size_t)b * HID + tid + 128];
                         sy[tid + 256] = xa[(size_t)b * HID + tid + 256]; }
    } else if (AOP == MAOP_CONCAT) {
        if (tid < 128) { sy[tid] = xb[(size_t)b * HID + tid];
                         sy[tid + 128] = xb[(size_t)b * HID + tid + 128];
                         sy[tid + 256] = xb[(size_t)b * HID + tid + 256]; }
    }

    float acc[2][8][4];
#pragma unroll
    for (int mf = 0; mf < 2; mf++)
#pragma unroll
        for (int nf = 0; nf < 8; nf++)
#pragma unroll
            for (int e = 0; e < 4; e++) acc[mf][nf][e] = 0.f;

    uint32_t aBaseH = smem_u32(sAh), aBaseL = smem_u32(sAl);
    uint32_t bBaseH = smem_u32(sBh), bBaseL = smem_u32(sBl);
    int aRow = wm * 32 + (lane & 15);
    int aK   = (lane & 16) >> 1;                              // 0 / 8
    int bRow = wn * 64 + ((lane & 16) >> 1) + (lane & 7);
    int bK   = lane & 8;

    // per-thread tile coordinates (2 iters per chunk)
    int arow0 = tid >> 2, ag8_0 = tid & 3;                    // it=0
    int arow1 = (tid + 256) >> 2, ag8_1 = (tid + 256) & 3;    // it=1

    // ---- A-only raw global prefetch (DRAM-latency path) ----
    float pA[2][8];
    auto loadA = [&](int kc) {
#pragma unroll
        for (int it = 0; it < 2; it++) {
            int row = it ? arow1 : arow0;
            int g8  = it ? ag8_1 : ag8_0;
            int gk  = kc * 32 + g8 * 8;
            const float4* p;
            if (AOP == MAOP_CONCAT && gk >= HID)
                p = (const float4*)(xa + (m0 + row) * HID + (gk - HID));
            else
                p = (const float4*)(A + (m0 + row) * HID + gk);
            float4 a0 = p[0], a1 = p[1];
            pA[it][0]=a0.x; pA[it][1]=a0.y; pA[it][2]=a0.z; pA[it][3]=a0.w;
            pA[it][4]=a1.x; pA[it][5]=a1.y; pA[it][6]=a1.z; pA[it][7]=a1.w;
        }
    };

    const uint4* bhp = (const uint4*)Bhi;
    const uint4* blp = (const uint4*)Blo;

    loadA(0);
    __syncthreads();          // sy visible before first STS reads it

    for (int kc = 0; kc < KCHN; kc++) {
        if (kc) __syncthreads();          // prior chunk's ldmatrix done before overwrite
        // ---- B load (L2-resident; synchronous) + STS of prologued A ----
#pragma unroll
        for (int it = 0; it < 2; it++) {
            int row = it ? arow1 : arow0;
            int g8  = it ? ag8_1 : ag8_0;
            int gk  = kc * 32 + g8 * 8;
            size_t gi = ((size_t)(bn + row) * K + kc * 32 + g8 * 8) >> 3;
            uint4 bhv = bhp[gi];
            uint4 blv = blp[gi];
            float v[8];
            if (AOP == MAOP_TANH) {
#pragma unroll
                for (int q = 0; q < 8; q++) v[q] = ftanh(pA[it][q]);
            } else if (AOP == MAOP_T0Y1) {
#pragma unroll
                for (int q = 0; q < 8; q++) v[q] = ftanh(pA[it][q] + sy[gk + q]);
            } else { // MAOP_CONCAT
                if (gk < HID) {
#pragma unroll
                    for (int q = 0; q < 8; q++) v[q] = pA[it][q];
                } else {
                    int k2 = gk - HID;
#pragma unroll
                    for (int q = 0; q < 8; q++) v[q] = pA[it][q] * sy[k2 + q];
                }
            }
            uint4 hu, lu;
            uint32_t* hw = (uint32_t*)&hu;
            uint32_t* lw = (uint32_t*)&lu;
#pragma unroll
            for (int q = 0; q < 4; q++) {
                __nv_bfloat16 h0 = __float2bfloat16(v[2*q]);
                __nv_bfloat16 h1 = __float2bfloat16(v[2*q+1]);
                float l0 = v[2*q]   - __bfloat162float(h0);
                float l1 = v[2*q+1] - __bfloat162float(h1);
                __nv_bfloat16 e0 = __float2bfloat16(l0), e1 = __float2bfloat16(l1);
                hw[q] = (uint32_t)__bfloat16_as_ushort(h0) | ((uint32_t)__bfloat16_as_ushort(h1) << 16);
                lw[q] = (uint32_t)__bfloat16_as_ushort(e0) | ((uint32_t)__bfloat16_as_ushort(e1) << 16);
            }
            *(uint4*)(sAh + row * LDS + g8 * 8) = hu;
            *(uint4*)(sAl + row * LDS + g8 * 8) = lu;
            *(uint4*)(sBh + row * LDS + g8 * 8) = bhv;
            *(uint4*)(sBl + row * LDS + g8 * 8) = blv;
        }
        __syncthreads();

        // ---- prefetch next chunk's A (overlaps with mma below) ----
        if (kc + 1 < KCHN) loadA(kc + 1);

        // ---- mma mainloop: 2 k16 steps ----
#pragma unroll
        for (int ks = 0; ks < 2; ks++) {
            uint32_t ah[2][4], al[2][4];
#pragma unroll
            for (int mf = 0; mf < 2; mf++) {
                uint32_t off = (uint32_t)(((aRow + mf * 16) * LDS + ks * 16 + aK) * 2);
                ldmx4(ah[mf], aBaseH + off);
                ldmx4(al[mf], aBaseL + off);
            }
#pragma unroll
            for (int f2 = 0; f2 < 4; f2++) {
                uint32_t boff = (uint32_t)(((bRow + f2 * 16) * LDS + ks * 16 + bK) * 2);
                uint32_t bh[4], bl[4];
                ldmx4(bh, bBaseH + boff);
                ldmx4(bl, bBaseL + boff);
#pragma unroll
                for (int j = 0; j < 2; j++) {
                    int nf = f2 * 2 + j;
#pragma unroll
                    for (int mf = 0; mf < 2; mf++) {
                        mma16816(acc[mf][nf], ah[mf], bh[2*j], bh[2*j+1]);
                        mma16816(acc[mf][nf], ah[mf], bl[2*j], bl[2*j+1]);
                        mma16816(acc[mf][nf], al[mf], bh[2*j], bh[2*j+1]);
                    }
                }
            }
        }
    }

    if (COP == 0) {
#pragma unroll
        for (int mf = 0; mf < 2; mf++) {
            int r0 = wm * 32 + mf * 16 + (lane >> 2);
#pragma unroll
            for (int nf = 0; nf < 8; nf++) {
                int col = bn + wn * 64 + nf * 8 + (lane & 3) * 2;
                *(float2*)(C + (m0 + r0) * Ntot + col)     = make_float2(acc[mf][nf][0], acc[mf][nf][1]);
                *(float2*)(C + (m0 + r0 + 8) * Ntot + col) = make_float2(acc[mf][nf][2], acc[mf][nf][3]);
            }
        }
    } else {
        // fused sigmoid + sf_fusion masked reduction over tokens -> C[b, bn:bn+128]
        int len = lens[b];
        float p[16];
#pragma unroll
        for (int i = 0; i < 16; i++) p[i] = 0.f;
#pragma unroll
        for (int nf = 0; nf < 8; nf++) {
            int hcol = bn + wn * 64 + nf * 8 + (lane & 3) * 2;
            float2 yv = *(const float2*)(xc + (size_t)b * HID + hcol);
            float ty0 = ftanh(yv.x), ty1 = ftanh(yv.y);
#pragma unroll
            for (int mf = 0; mf < 2; mf++) {
#pragma unroll
                for (int rh = 0; rh < 2; rh++) {
                    int l = wm * 32 + mf * 16 + (lane >> 2) + rh * 8;
                    if (l < len) {
                        float2 cv = *(const float2*)(xb + (m0 + l) * HID + hcol);
                        float f0 = fsig(acc[mf][nf][rh*2]);
                        float f1 = fsig(acc[mf][nf][rh*2+1]);
                        float o0 = 1.f - f0, o1 = 1.f - f1;
                        p[nf*2]   += f0 * (f0 * ftanh(cv.x) + cv.x) + o0 * (o0 * ty0 + yv.x);
                        p[nf*2+1] += f1 * (f1 * ftanh(cv.y) + cv.y) + o1 * (o1 * ty1 + yv.y);
                    }
                }
            }
        }
#pragma unroll
        for (int i = 0; i < 16; i++) {
            p[i] += __shfl_xor_sync(0xffffffffu, p[i], 4);
            p[i] += __shfl_xor_sync(0xffffffffu, p[i], 8);
            p[i] += __shfl_xor_sync(0xffffffffu, p[i], 16);
        }
        float* red = (float*)tiles[0];      // reuse tile smem (all reads done)
        __syncthreads();
        if (lane < 4) {
#pragma unroll
            for (int nf = 0; nf < 8; nf++) {
                red[wm * 128 + wn * 64 + nf * 8 + lane * 2]     = p[nf*2];
                red[wm * 128 + wn * 64 + nf * 8 + lane * 2 + 1] = p[nf*2+1];
            }
        }
        __syncthreads();
        if (tid < 128)
            C[(size_t)b * HID + bn + tid] = red[tid] + red[128 + tid] + red[256 + tid] + red[384 + tid];
    }
}

// ---------------- weight pre-split (transpose + bf16 hi/lo) ----------------
__global__ void k_wconv(const float* __restrict__ W, __nv_bfloat16* __restrict__ hi,
                        __nv_bfloat16* __restrict__ lo, int Kd, int Nd) {
    int idx = blockIdx.x * 256 + threadIdx.x;
    if (idx >= Kd * Nd) return;
    int n = idx / Kd, k = idx % Kd;          // output [N][K]
    float v = W[(size_t)k * Nd + n];
    __nv_bfloat16 h = __float2bfloat16(v);
    hi[idx] = h;
    lo[idx] = __float2bfloat16(v - __bfloat162float(h));
}

// ---------------- SIMT GEMM for the small [512,384,384] cases ----------------
enum { AOP_ID = 0, AOP_TANH = 1 };
template <int BM, int BN, int BK, int TM, int TN, int AOP>
__global__ void __launch_bounds__((BM / TM) * (BN / TN))
gemm_small(const float* __restrict__ A, const float* __restrict__ Bm,
           float* __restrict__ C, int M, int N, int K) {
    constexpr int THREADS = (BM / TM) * (BN / TN);
    constexpr int AV = BK / 4, ALOADS = (BM * AV) / THREADS, ARSTEP = THREADS / AV;
    constexpr int BV = BN / 4, BLOADS = (BK * BV) / THREADS, BRSTEP = THREADS / BV;
    __shared__ __align__(16) float As[BK][BM];
    __shared__ __align__(16) float Bs[BK][BN];
    int tid = threadIdx.x, bm = blockIdx.y * BM, bn = blockIdx.x * BN;
    int trow = tid / (BN / TN), tcol = tid % (BN / TN);
    int ar = tid / AV, ac = (tid % AV) * 4;
    int br = tid / BV, bc = (tid % BV) * 4;

    auto fetchA = [&](int row, int k) -> float4 {
        float4 v = *(const float4*)&A[(size_t)row * K + k];
        if (AOP == AOP_TANH) { v.x=ftanh(v.x); v.y=ftanh(v.y); v.z=ftanh(v.z); v.w=ftanh(v.w); }
        return v;
    };
    float4 aReg[ALOADS], bReg[BLOADS];
#pragma unroll
    for (int i = 0; i < ALOADS; i++) aReg[i] = fetchA(bm + ar + i * ARSTEP, ac);
#pragma unroll
    for (int i = 0; i < BLOADS; i++) bReg[i] = *(const float4*)&Bm[(size_t)(br + i * BRSTEP) * N + bn + bc];
    float acc[TM][TN] = {};
    for (int k0 = 0; k0 < K; k0 += BK) {
#pragma unroll
        for (int i = 0; i < ALOADS; i++) {
            int r = ar + i * ARSTEP;
            As[ac+0][r]=aReg[i].x; As[ac+1][r]=aReg[i].y; As[ac+2][r]=aReg[i].z; As[ac+3][r]=aReg[i].w;
        }
#pragma unroll
        for (int i = 0; i < BLOADS; i++) *(float4*)&Bs[br + i * BRSTEP][bc] = bReg[i];
        __syncthreads();
        int k1 = k0 + BK;
        if (k1 < K) {
#pragma unroll
            for (int i = 0; i < ALOADS; i++) aReg[i] = fetchA(bm + ar + i * ARSTEP, k1 + ac);
#pragma unroll
            for (int i = 0; i < BLOADS; i++) bReg[i] = *(const float4*)&Bm[(size_t)(k1 + br + i * BRSTEP) * N + bn + bc];
        }
#pragma unroll
        for (int kk = 0; kk < BK; kk++) {
            float ra[TM], rb[TN];
#pragma unroll
            for (int i = 0; i < TM; i += 4) *(float4*)&ra[i] = *(const float4*)&As[kk][trow * TM + i];
#pragma unroll
            for (int j = 0; j < TN; j += 4) *(float4*)&rb[j] = *(const float4*)&Bs[kk][tcol * TN + j];
#pragma unroll
            for (int i = 0; i < TM; i++)
#pragma unroll
                for (int j = 0; j < TN; j++) acc[i][j] = fmaf(ra[i], rb[j], acc[i][j]);
        }
        __syncthreads();
    }
#pragma unroll
    for (int i = 0; i < TM; i++) {
        int row = bm + trow * TM + i;
#pragma unroll
        for (int j = 0; j < TN; j += 4)
            *(float4*)&C[(size_t)row * N + bn + tcol * TN + j] =
                make_float4(acc[i][j], acc[i][j+1], acc[i][j+2], acc[i][j+3]);
    }
}

// ---------------- small kernels ----------------
__global__ void k_prep(const float* __restrict__ W3, const float* __restrict__ W4,
                       const float* __restrict__ b4, const float* __restrict__ W5) {
    int t = threadIdx.x;
    float v3 = 0.f, v4 = 0.f;
    for (int j = 0; j < HID; j++) {
        float w5 = W5[j];
        v3 += W3[t * HID + j] * w5;
        v4 += W4[t * HID + j] * w5;
    }
    g_w3v[t] = v3; g_w4v[t] = v4;
    if (t == 0) {
        float s = 0.f;
        for (int j = 0; j < HID; j++) s += b4[j] * W5[j];
        g_b4v = s;
    }
}

__global__ void k_hdot(const float* __restrict__ H) {
    int row = blockIdx.x * 8 + (threadIdx.x >> 5);
    int lane = threadIdx.x & 31;
    const float* hp = H + (size_t)row * HID;
    float v = 0.f;
    for (int h = lane; h < HID; h += 32) v += hp[h] * g_w4v[h];
#pragma unroll
    for (int o = 16; o > 0; o >>= 1) v += __shfl_down_sync(0xffffffffu, v, o);
    if (lane == 0) g_hdot[row] = v + g_b4v;
}

__global__ void k_idfuse(const float* __restrict__ Cs, const float* __restrict__ H,
                         const float* __restrict__ c_inte, const int* __restrict__ lens) {
    __shared__ float sr[LL];
    __shared__ float red[128];
    __shared__ float sal[LL];
    int b = blockIdx.x, t = threadIdx.x;
    int lane = t & 31, w = t >> 5;
    int len = lens[b];
    for (int l = w; l < LL; l += 12) {
        if (l < len) {
            const float* cp = Cs + ((size_t)b * LL + l) * HID;
            float v = 0.f;
            for (int hh = lane; hh < HID; hh += 32)
                v += g_g[b * HID + hh] * g_w3v[hh] * cp[hh];
#pragma unroll
            for (int o = 16; o > 0; o >>= 1) v += __shfl_down_sync(0xffffffffu, v, o);
            if (lane == 0) sr[l] = v + g_hdot[b * LL + l];
        } else if (lane == 0) sr[l] = -FLT_MAX;
    }
    __syncthreads();
    float rv = (t < 128) ? sr[t] : -FLT_MAX;
    if (t < 128) red[t] = rv;
    __syncthreads();
    for (int s = 64; s > 0; s >>= 1) { if (t < s) red[t] = fmaxf(red[t], red[t + s]); __syncthreads(); }
    float m = red[0];
    __syncthreads();
    float e = (t < 128) ? __expf(rv - m) : 0.f;
    if (t < 128) red[t] = e;
    __syncthreads();
    for (int s = 64; s > 0; s >>= 1) { if (t < s) red[t] += red[t + s]; __syncthreads(); }
    float sinv = __fdividef(1.0f, red[0]);
    if (t < 128) sal[t] = e * sinv;
    __syncthreads();
    int h = t;
    float gh = g_g[b * HID + h];
    const float* cp = Cs + (size_t)b * LL * HID + h;
    const float* hp = H + (size_t)b * LL * HID + h;
    float acc = 0.f;
    for (int l = 0; l < len; l++) {
        float a = sal[l];
        float cv = cp[(size_t)l * HID];
        float Hv = hp[(size_t)l * HID];
        float x = gh * cv;
        float oma = 1.0f - a;
        acc += a * (a * ftanh(x) + x) + oma * (oma * ftanh(Hv) + Hv);
    }
    g_rin[b * HID + h] = acc + c_inte[b * HID + h];
}

__global__ void k_intent(const float* __restrict__ Wi, float* __restrict__ out) {
    int n = threadIdx.x;
    int b = blockIdx.x * blockDim.y + threadIdx.y;
    float v = 0.f;
    for (int k = 0; k < HID; k++) v += g_rin[b * HID + k] * Wi[k * NLAB + n];
    out[b * NLAB + n] = v;
}

// ---------------- launch ----------------
extern "C" void kernel_launch(void* const* d_in, const int* in_sizes, int n_in,
                              void* d_out, int out_size) {
    const float* H      = (const float*)d_in[0];
    const float* Cs     = (const float*)d_in[1];
    const float* c_inte = (const float*)d_in[2];
    const float* W0     = (const float*)d_in[3];
    const float* W1     = (const float*)d_in[4];
    const float* W2     = (const float*)d_in[5];
    const float* W3     = (const float*)d_in[6];
    const float* W4     = (const float*)d_in[7];
    const float* b4     = (const float*)d_in[8];
    const float* W5     = (const float*)d_in[9];
    const float* V_SF   = (const float*)d_in[10];
    const float* W_inte = (const float*)d_in[11];
    const float* W_slot = (const float*)d_in[12];
    const int*   lens   = (const int*)d_in[13];
    float* out = (float*)d_out;

    float *pT0, *pS, *pY1, *pG, *pRin;
    __nv_bfloat16 *pW0h, *pW0l, *pW2h, *pW2l, *pWsh, *pWsl;
    cudaGetSymbolAddress((void**)&pT0,  g_T0);
    cudaGetSymbolAddress((void**)&pS,   g_S);
    cudaGetSymbolAddress((void**)&pY1,  g_y1);
    cudaGetSymbolAddress((void**)&pG,   g_g);
    cudaGetSymbolAddress((void**)&pRin, g_rin);
    cudaGetSymbolAddress((void**)&pW0h, g_W0h); cudaGetSymbolAddress((void**)&pW0l, g_W0l);
    cudaGetSymbolAddress((void**)&pW2h, g_W2h); cudaGetSymbolAddress((void**)&pW2l, g_W2l);
    cudaGetSymbolAddress((void**)&pWsh, g_Wsh); cudaGetSymbolAddress((void**)&pWsl, g_Wsl);

    // precompute (iteration-invariant)
    k_prep<<<1, HID>>>(W3, W4, b4, W5);
    k_hdot<<<NROWS / 8, 256>>>(H);
    k_wconv<<<(HID * HID + 255) / 256, 256>>>(W0, pW0h, pW0l, HID, HID);
    k_wconv<<<(HID * HID + 255) / 256, 256>>>(W2, pW2h, pW2l, HID, HID);
    k_wconv<<<(2 * HID * NSLOT + 255) / 256, 256>>>(W_slot, pWsh, pWsl, 2 * HID, NSLOT);
    // T0 = tanh(Cs) @ W0
    wmma_big<12, MAOP_TANH, 0><<<dim3(HID / 128, BB), 256>>>(
        Cs, pW0h, pW0l, pT0, HID, nullptr, nullptr, nullptr, nullptr);
    cudaMemcpyAsync(pRin, c_inte, (size_t)BB * HID * sizeof(float), cudaMemcpyDeviceToDevice);

    for (int it = 0; it < ITERS; ++it) {
        // y1 = tanh(r_inte) @ W1
        gemm_small<32, 64, 16, 4, 4, AOP_TANH>
            <<<dim3(HID / 64, BB / 32), 128>>>(pRin, W1, pY1, BB, HID, HID);
        // S[b,:] = sum_l sf_fusion(sigmoid(tanh(T0 + y1[b]) @ W2), ...) — tensor-core + fused reduce
        wmma_big<12, MAOP_T0Y1, 1><<<dim3(HID / 128, BB), 256>>>(
            pT0, pW2h, pW2l, pS, HID, pY1, Cs, pRin, lens);
        // g = S @ V_SF
        gemm_small<32, 64, 16, 4, 4, AOP_ID>
            <<<dim3(HID / 64, BB / 32), 128>>>(pS, V_SF, pG, BB, HID, HID);
        k_idfuse<<<BB, HID>>>(Cs, H, c_inte, lens);
    }

    k_intent<<<BB / 8, dim3(NLAB, 8)>>>(W_inte, out);
    // slot_output = [H | g (x) c] @ W_slot — tensor-core, concat in prologue
    wmma_big<24, MAOP_CONCAT, 0><<<dim3(NSLOT / 128, BB), 256>>>(
        H, pWsh, pWsl, out + BB * NLAB, NSLOT, Cs, pG, nullptr, nullptr);
}